// round 12
// baseline (speedup 1.0000x reference)
#include <cuda_runtime.h>

// Chamfer distance, pc1/pc2: (1, 16384, 3) fp32 -> scalar fp32.
// R12: x-sorted NN search with threshold-capped early exit (d2>=2 -> 0 lets
//      best init at 2.0). Bin sort (4096 bins) + warp-per-query two-sided scan.
//      ~24x fewer distance evals than brute force.

#define NP     16384
#define NB     4096
#define XMIN   (-6.0f)
#define XRANGE (12.0f)
#define BWID   (XRANGE / NB)        // 0.00293
#define INVBW  (NB / XRANGE)

#define NNTHR  512
#define NNBLK  592                  // 592*16 = 9472 warps

__device__ float4 s_pts[2][NP];     // sorted by x-bin; w = original index bits
__device__ int    bin_cnt[2][NB];
__device__ int    bin_start[2][NB];
__device__ int    scatter_pos[2][NB];
__device__ float  g_d[2 * NP];      // per-original-index NN d2 (capped at 2.0)

#define REDUX_MIN_S32(out, in) \
    asm("redux.sync.min.s32 %0, %1, 0xffffffff;" : "=r"(out) : "r"(in))

__device__ __forceinline__ int xbin(float x) {
    int b = (int)((x - XMIN) * INVBW);
    return min(max(b, 0), NB - 1);
}

__global__ void zero_kernel() {
    int i = blockIdx.x * blockDim.x + threadIdx.x;
    if (i < 2 * NB) ((int*)bin_cnt)[i] = 0;
}

__global__ void hist_kernel(const float* __restrict__ pc1,
                            const float* __restrict__ pc2) {
    int i = blockIdx.x * blockDim.x + threadIdx.x;     // 0..2NP-1
    int dir = i >> 14, idx = i & (NP - 1);
    const float* pc = dir ? pc2 : pc1;
    atomicAdd(&bin_cnt[dir][xbin(pc[3 * idx])], 1);
}

// One block, 1024 threads: exclusive prefix over 4096 bins, both dirs.
__global__ void __launch_bounds__(1024) scan_kernel() {
    __shared__ int wsum[32];
    int tid = threadIdx.x, lane = tid & 31, wid = tid >> 5;
#pragma unroll 1
    for (int dir = 0; dir < 2; dir++) {
        int base = tid * 4;
        int c0 = bin_cnt[dir][base + 0], c1 = bin_cnt[dir][base + 1];
        int c2 = bin_cnt[dir][base + 2], c3 = bin_cnt[dir][base + 3];
        int s0 = c0, s1 = s0 + c1, s2 = s1 + c2, s3 = s2 + c3;
        int tot = s3, v = tot;
#pragma unroll
        for (int o = 1; o < 32; o <<= 1) {
            int u = __shfl_up_sync(0xffffffffu, v, o);
            if (lane >= o) v += u;
        }
        if (lane == 31) wsum[wid] = v;
        __syncthreads();
        if (wid == 0) {
            int w = wsum[lane];
#pragma unroll
            for (int o = 1; o < 32; o <<= 1) {
                int u = __shfl_up_sync(0xffffffffu, w, o);
                if (lane >= o) w += u;
            }
            wsum[lane] = w;                    // inclusive warp totals
        }
        __syncthreads();
        int warp_excl = (wid == 0) ? 0 : wsum[wid - 1];
        int ebase = warp_excl + (v - tot);     // exclusive for this thread
        bin_start[dir][base + 0] = ebase;
        bin_start[dir][base + 1] = ebase + s0;
        bin_start[dir][base + 2] = ebase + s1;
        bin_start[dir][base + 3] = ebase + s2;
        scatter_pos[dir][base + 0] = ebase;
        scatter_pos[dir][base + 1] = ebase + s0;
        scatter_pos[dir][base + 2] = ebase + s1;
        scatter_pos[dir][base + 3] = ebase + s2;
        __syncthreads();
    }
}

__global__ void scatter_kernel(const float* __restrict__ pc1,
                               const float* __restrict__ pc2) {
    int i = blockIdx.x * blockDim.x + threadIdx.x;
    int dir = i >> 14, idx = i & (NP - 1);
    const float* pc = dir ? pc2 : pc1;
    float x = pc[3 * idx], y = pc[3 * idx + 1], z = pc[3 * idx + 2];
    int pos = atomicAdd(&scatter_pos[dir][xbin(x)], 1);
    s_pts[dir][pos] = make_float4(x, y, z, __int_as_float(idx));
}

// Warp-per-query two-sided scan over the x-sorted other cloud.
// Lanes 0-15 scan left (j decreasing), 16-31 right. 2 chunks per termination
// check. Side stop: (|dx_extreme| - BWID)^2 >= best is safe because bin index
// is monotone along the sorted array (within-bin x error <= BWID).
__global__ void __launch_bounds__(NNTHR) nn_kernel() {
    const int lane = threadIdx.x & 31;
    const int gw   = blockIdx.x * (NNTHR / 32) + (threadIdx.x >> 5);
    const int NW   = NNBLK * (NNTHR / 32);
    const bool leftside = lane < 16;

    for (int t = gw; t < 2 * NP; t += NW) {
        int dir = t >> 14, q = t & (NP - 1);
        float4 p = s_pts[dir][q];
        const float4* __restrict__ R = s_pts[dir ^ 1];
        int j0 = bin_start[dir ^ 1][xbin(p.x)];

        int j    = leftside ? (j0 - 1 - lane) : (j0 + lane - 16);
        int step = leftside ? -16 : 16;
        float m = 2.0f;                       // threshold cap doubles as init
        bool sL = false, sR = false;

        while (true) {
            float dxa = 1e30f;
            bool mydone = leftside ? sL : sR;
#pragma unroll
            for (int u = 0; u < 2; u++) {
                if (!mydone && j >= 0 && j < NP) {
                    float4 r = R[j];
                    float dx = r.x - p.x, dy = r.y - p.y, dz = r.z - p.z;
                    float d2 = fmaf(dx, dx, fmaf(dy, dy, dz * dz));
                    m = fminf(m, d2);
                    dxa = fabsf(dx);          // farthest substep wins (kept last)
                } else {
                    dxa = 1e30f;              // OOR/done: forces side stop
                }
                j += step;
            }
            int mb; REDUX_MIN_S32(mb, __float_as_int(m));
            float best = __int_as_float(mb);
            float extL = __shfl_sync(0xffffffffu, dxa, 15);
            float extR = __shfl_sync(0xffffffffu, dxa, 31);
            float bl = extL - BWID, br = extR - BWID;
            if (bl > 0.0f && bl * bl >= best) sL = true;
            if (br > 0.0f && br * br >= best) sR = true;
            if (sL && sR) break;
        }
        int mb; REDUX_MIN_S32(mb, __float_as_int(m));
        if (lane == 0)
            g_d[dir * NP + __float_as_int(p.w)] = __int_as_float(mb);
    }
}

// Fixed-order deterministic sum with threshold.
__global__ void __launch_bounds__(1024) reduce_kernel(float* __restrict__ out)
{
    const int tid = threadIdx.x;
    float s = 0.0f;
#pragma unroll
    for (int k = 0; k < (2 * NP) / 1024; k++) {
        float d = g_d[tid + k * 1024];
        if (d < 2.0f) s += d;                 // >=2 (incl. untouched cap) -> 0
    }
#pragma unroll
    for (int o = 16; o; o >>= 1) s += __shfl_xor_sync(0xFFFFFFFFu, s, o);

    __shared__ float ws[32];
    if ((tid & 31) == 0) ws[tid >> 5] = s;
    __syncthreads();
    if (tid < 32) {
        float v = ws[tid];
#pragma unroll
        for (int o = 16; o; o >>= 1) v += __shfl_xor_sync(0xFFFFFFFFu, v, o);
        if (tid == 0) out[0] = v * (1.0f / (float)NP);
    }
}

extern "C" void kernel_launch(void* const* d_in, const int* in_sizes, int n_in,
                              void* d_out, int out_size)
{
    const float* pc1 = (const float*)d_in[0];
    const float* pc2 = (const float*)d_in[1];
    float* out = (float*)d_out;

    zero_kernel<<<(2 * NB + 1023) / 1024, 1024>>>();
    hist_kernel<<<(2 * NP) / 1024, 1024>>>(pc1, pc2);
    scan_kernel<<<1, 1024>>>();
    scatter_kernel<<<(2 * NP) / 1024, 1024>>>(pc1, pc2);
    nn_kernel<<<NNBLK, NNTHR>>>();
    reduce_kernel<<<1, 1024>>>(out);
}